// round 2
// baseline (speedup 1.0000x reference)
#include <cuda_runtime.h>
#include <math.h>

#define HIN     14
#define WIN     14
#define HO      12
#define WO      12
#define BATCH   4
#define FIN     32
#define DIN     8
#define FF      32
#define CCAP    288
#define DOUT    16
#define NPOS    (BATCH*HO*WO)   // 576

// pass1: 12 warps, 4 positions/warp, 12 c-chunks of 24 -> grid 12x12 = 144
#define TPB1    384
#define POSB1   48
#define NPB1    (NPOS/POSB1)    // 12
#define NCH1    12
#define CPC1    (CCAP/NCH1)     // 24

// pass2: 8 warps, 2 positions/warp, 4 c-chunks of 72 -> grid 36x4 = 144
#define TPB2    256
#define POSB2   16
#define NPB2    (NPOS/POSB2)    // 36
#define NCH2    4
#define CPC2    (CCAP/NCH2)     // 72

// ---------------- scratch (static device globals; no allocation) -------------
__device__ float g_Wt[(size_t)CCAP*32*32*4];            // [c][jv(32)][f(32)] float4 units
__device__ float g_S1p[(size_t)NCH1*NPOS*FF*DOUT];      // pass1 partials
__device__ float g_out1[(size_t)NPOS*FF*DOUT];          // squash(centroid iter1)
__device__ float g_centp[(size_t)NCH2*NPOS*FF*DOUT];    // pass2 partial centroids

// patch base-offset LUT: (kh*WIN+kw)*FIN*DIN for kk = kh*3+kw
__device__ __constant__ int c_koff[9] = {0, 256, 512, 3584, 3840, 4096, 7168, 7424, 7680};

// ---------------- W transpose: W[f][c][o][i] -> Wt[c][jv][f] ------------------
__global__ void k_transpose(const float* __restrict__ W) {
    int tid = blockIdx.x * blockDim.x + threadIdx.x;
    if (tid >= CCAP * FF * 32) return;
    int jv = tid & 31;
    int f  = (tid >> 5) & 31;
    int c  = tid >> 10;
    float4 v = ((const float4*)W)[((size_t)f * CCAP + c) * 32 + jv];
    ((float4*)g_Wt)[((size_t)c * 32 + jv) * 32 + f] = v;
}

__device__ __forceinline__ const float* pos_base(const float* x, int pos) {
    int b = pos / (HO * WO);
    int r = pos % (HO * WO);
    int h = r / WO;
    int w = r % WO;
    return x + (((size_t)(b * HIN + h) * WIN) + w) * (FIN * DIN);
}

// ---- pred for 2 positions, one c; lane = f --------------------------------
__device__ __forceinline__ void pred_c2(int c, const float* xb0, const float* xb1,
                                        int lane, float pr0[DOUT], float pr1[DOUT]) {
    int off = c_koff[c >> 5] + (c & 31) * DIN;
    const float4* xp0 = (const float4*)(xb0 + off);
    const float4* xp1 = (const float4*)(xb1 + off);
    float4 a0 = xp0[0], a1 = xp0[1];
    float4 b0 = xp1[0], b1 = xp1[1];
    const float4* wp = ((const float4*)g_Wt) + (size_t)c * 1024 + lane;
    #pragma unroll 8
    for (int o = 0; o < DOUT; ++o) {
        float4 w0 = wp[(size_t)(2*o) * 32];
        float4 w1 = wp[(size_t)(2*o+1) * 32];
        pr0[o] += w0.x*a0.x + w0.y*a0.y + w0.z*a0.z + w0.w*a0.w
                + w1.x*a1.x + w1.y*a1.y + w1.z*a1.z + w1.w*a1.w;
        pr1[o] += w0.x*b0.x + w0.y*b0.y + w0.z*b0.z + w0.w*b0.w
                + w1.x*b1.x + w1.y*b1.y + w1.z*b1.z + w1.w*b1.w;
    }
}

// ---- pred for 4 positions, one c -------------------------------------------
__device__ __forceinline__ void pred_c4(int c,
        const float* xb0, const float* xb1, const float* xb2, const float* xb3,
        int lane, float p0[DOUT], float p1[DOUT], float p2[DOUT], float p3[DOUT]) {
    int off = c_koff[c >> 5] + (c & 31) * DIN;
    const float4* xp0 = (const float4*)(xb0 + off);
    const float4* xp1 = (const float4*)(xb1 + off);
    const float4* xp2 = (const float4*)(xb2 + off);
    const float4* xp3 = (const float4*)(xb3 + off);
    float4 a0 = xp0[0], a1 = xp0[1];
    float4 b0 = xp1[0], b1 = xp1[1];
    float4 c0 = xp2[0], c1 = xp2[1];
    float4 d0 = xp3[0], d1 = xp3[1];
    const float4* wp = ((const float4*)g_Wt) + (size_t)c * 1024 + lane;
    #pragma unroll 4
    for (int o = 0; o < DOUT; ++o) {
        float4 w0 = wp[(size_t)(2*o) * 32];
        float4 w1 = wp[(size_t)(2*o+1) * 32];
        p0[o] += w0.x*a0.x + w0.y*a0.y + w0.z*a0.z + w0.w*a0.w
               + w1.x*a1.x + w1.y*a1.y + w1.z*a1.z + w1.w*a1.w;
        p1[o] += w0.x*b0.x + w0.y*b0.y + w0.z*b0.z + w0.w*b0.w
               + w1.x*b1.x + w1.y*b1.y + w1.z*b1.z + w1.w*b1.w;
        p2[o] += w0.x*c0.x + w0.y*c0.y + w0.z*c0.z + w0.w*c0.w
               + w1.x*c1.x + w1.y*c1.y + w1.z*c1.z + w1.w*c1.w;
        p3[o] += w0.x*d0.x + w0.y*d0.y + w0.z*d0.z + w0.w*d0.w
               + w1.x*d1.x + w1.y*d1.y + w1.z*d1.z + w1.w*d1.w;
    }
}

// ---------------- pass 1: partial sum over c of preds (4 pos/warp) ----------
__global__ void __launch_bounds__(TPB1, 1) k_pass1(const float* __restrict__ x) {
    int lane = threadIdx.x & 31;
    int w    = threadIdx.x >> 5;
    int pos0 = blockIdx.x * POSB1 + w * 4;
    int cch  = blockIdx.y;
    const float* xb0 = pos_base(x, pos0);
    const float* xb1 = pos_base(x, pos0 + 1);
    const float* xb2 = pos_base(x, pos0 + 2);
    const float* xb3 = pos_base(x, pos0 + 3);

    float a0[DOUT], a1[DOUT], a2[DOUT], a3[DOUT];
    #pragma unroll
    for (int o = 0; o < DOUT; ++o) { a0[o]=0.f; a1[o]=0.f; a2[o]=0.f; a3[o]=0.f; }

    int cbeg = cch * CPC1;
    for (int c = cbeg; c < cbeg + CPC1; ++c)
        pred_c4(c, xb0, xb1, xb2, xb3, lane, a0, a1, a2, a3);

    float* base = g_S1p + ((size_t)cch * NPOS + pos0) * FF * DOUT + (size_t)lane * DOUT;
    #pragma unroll
    for (int q = 0; q < 4; ++q) {
        ((float4*)base)[q]                    = make_float4(a0[q*4],a0[q*4+1],a0[q*4+2],a0[q*4+3]);
        ((float4*)(base + FF*DOUT))[q]        = make_float4(a1[q*4],a1[q*4+1],a1[q*4+2],a1[q*4+3]);
        ((float4*)(base + 2*FF*DOUT))[q]      = make_float4(a2[q*4],a2[q*4+1],a2[q*4+2],a2[q*4+3]);
        ((float4*)(base + 3*FF*DOUT))[q]      = make_float4(a3[q*4],a3[q*4+1],a3[q*4+2],a3[q*4+3]);
    }
}

// ---------------- squash 1 ---------------------------------------------------
__global__ void k_squash1() {
    int t = blockIdx.x * blockDim.x + threadIdx.x;   // (pos,f)
    if (t >= NPOS * FF) return;
    float s[DOUT];
    #pragma unroll
    for (int o = 0; o < DOUT; ++o) s[o] = 0.f;
    for (int ch = 0; ch < NCH1; ++ch) {
        const float* p = g_S1p + ((size_t)ch * NPOS * FF + t) * DOUT;
        #pragma unroll
        for (int o = 0; o < DOUT; ++o) s[o] += p[o];
    }
    float sn = 0.f;
    #pragma unroll
    for (int o = 0; o < DOUT; ++o) { s[o] *= (1.f/32.f); sn += s[o]*s[o]; }
    float sc = (sn / (1.f + sn)) / sqrtf(sn + 1e-7f);
    float* d = g_out1 + (size_t)t * DOUT;
    #pragma unroll
    for (int o = 0; o < DOUT; ++o) d[o] = s[o] * sc;
}

// ---------------- pass 2: fused agreement/softmax(F)/centroid, 2 c's piped --
__global__ void __launch_bounds__(TPB2, 1) k_pass2(const float* __restrict__ x) {
    int lane = threadIdx.x & 31;
    int w    = threadIdx.x >> 5;
    int pos0 = blockIdx.x * POSB2 + w * 2;
    int pos1 = pos0 + 1;
    int cch  = blockIdx.y;
    const float* xb0 = pos_base(x, pos0);
    const float* xb1 = pos_base(x, pos1);

    float o10[DOUT], o11[DOUT];
    {
        const float* q0 = g_out1 + (((size_t)pos0 * FF) + lane) * DOUT;
        const float* q1 = g_out1 + (((size_t)pos1 * FF) + lane) * DOUT;
        #pragma unroll
        for (int o = 0; o < DOUT; ++o) { o10[o] = q0[o]; o11[o] = q1[o]; }
    }

    float ce0[DOUT], ce1[DOUT];
    #pragma unroll
    for (int o = 0; o < DOUT; ++o) { ce0[o] = 0.f; ce1[o] = 0.f; }

    int cbeg = cch * CPC2;
    for (int c = cbeg; c < cbeg + CPC2; c += 2) {
        float pA0[DOUT], pA1[DOUT], pB0[DOUT], pB1[DOUT];
        #pragma unroll
        for (int o = 0; o < DOUT; ++o) { pA0[o]=0.f; pA1[o]=0.f; pB0[o]=0.f; pB1[o]=0.f; }
        pred_c2(c,     xb0, xb1, lane, pA0, pA1);
        pred_c2(c + 1, xb0, xb1, lane, pB0, pB1);

        // agreement dots with 4-way partial trees (shorter dep chains)
        float eA0, eA1, eB0, eB1;
        {
            float t0=0.f,t1=0.f,t2=0.f,t3=0.f;
            float u0=0.f,u1=0.f,u2=0.f,u3=0.f;
            float v0=0.f,v1=0.f,v2=0.f,v3=0.f;
            float z0=0.f,z1=0.f,z2=0.f,z3=0.f;
            #pragma unroll
            for (int q = 0; q < 4; ++q) {
                t0 += pA0[q]*o10[q];      t1 += pA0[q+4]*o10[q+4];
                t2 += pA0[q+8]*o10[q+8];  t3 += pA0[q+12]*o10[q+12];
                u0 += pA1[q]*o11[q];      u1 += pA1[q+4]*o11[q+4];
                u2 += pA1[q+8]*o11[q+8];  u3 += pA1[q+12]*o11[q+12];
                v0 += pB0[q]*o10[q];      v1 += pB0[q+4]*o10[q+4];
                v2 += pB0[q+8]*o10[q+8];  v3 += pB0[q+12]*o10[q+12];
                z0 += pB1[q]*o11[q];      z1 += pB1[q+4]*o11[q+4];
                z2 += pB1[q+8]*o11[q+8];  z3 += pB1[q+12]*o11[q+12];
            }
            // no max-subtraction: |agreement| is O(1), exp is safe in fp32
            eA0 = __expf((t0+t1)+(t2+t3));
            eA1 = __expf((u0+u1)+(u2+u3));
            eB0 = __expf((v0+v1)+(v2+v3));
            eB1 = __expf((z0+z1)+(z2+z3));
        }

        // 4 independent butterfly sums over f (lanes), fully pipelined
        float sA0 = eA0, sA1 = eA1, sB0 = eB0, sB1 = eB1;
        #pragma unroll
        for (int d = 16; d > 0; d >>= 1) {
            sA0 += __shfl_xor_sync(0xffffffffu, sA0, d);
            sA1 += __shfl_xor_sync(0xffffffffu, sA1, d);
            sB0 += __shfl_xor_sync(0xffffffffu, sB0, d);
            sB1 += __shfl_xor_sync(0xffffffffu, sB1, d);
        }
        float cA0 = __fdividef(eA0, sA0);
        float cA1 = __fdividef(eA1, sA1);
        float cB0 = __fdividef(eB0, sB0);
        float cB1 = __fdividef(eB1, sB1);

        #pragma unroll
        for (int o = 0; o < DOUT; ++o) {
            ce0[o] += cA0 * pA0[o] + cB0 * pB0[o];
            ce1[o] += cA1 * pA1[o] + cB1 * pB1[o];
        }
    }

    float* base = g_centp + ((size_t)cch * NPOS + pos0) * FF * DOUT + (size_t)lane * DOUT;
    #pragma unroll
    for (int q = 0; q < 4; ++q) {
        ((float4*)base)[q]             = make_float4(ce0[q*4],ce0[q*4+1],ce0[q*4+2],ce0[q*4+3]);
        ((float4*)(base + FF*DOUT))[q] = make_float4(ce1[q*4],ce1[q*4+1],ce1[q*4+2],ce1[q*4+3]);
    }
}

// ---------------- squash 2: final output ------------------------------------
__global__ void k_squash2(float* __restrict__ out) {
    int t = blockIdx.x * blockDim.x + threadIdx.x;   // (pos,f)
    if (t >= NPOS * FF) return;
    float s[DOUT];
    #pragma unroll
    for (int o = 0; o < DOUT; ++o) s[o] = 0.f;
    for (int ch = 0; ch < NCH2; ++ch) {
        const float* p = g_centp + ((size_t)ch * NPOS * FF + t) * DOUT;
        #pragma unroll
        for (int o = 0; o < DOUT; ++o) s[o] += p[o];
    }
    float sn = 0.f;
    #pragma unroll
    for (int o = 0; o < DOUT; ++o) sn += s[o]*s[o];
    float sc = (sn / (1.f + sn)) / sqrtf(sn + 1e-7f);
    float* d = out + (size_t)t * DOUT;
    #pragma unroll
    for (int o = 0; o < DOUT; ++o) d[o] = s[o] * sc;
}

// -----------------------------------------------------------------------------
extern "C" void kernel_launch(void* const* d_in, const int* in_sizes, int n_in,
                              void* d_out, int out_size) {
    const float* x = (const float*)d_in[0];
    const float* W = (const float*)d_in[1];
    if (n_in >= 2 && in_sizes[0] == (int)((size_t)FF * CCAP * DOUT * DIN)) {
        const float* t = x; x = W; W = t;
    }
    float* out = (float*)d_out;

    k_transpose<<<(CCAP * FF * 32 + 255) / 256, 256>>>(W);
    k_pass1<<<dim3(NPB1, NCH1), TPB1>>>(x);
    k_squash1<<<(NPOS * FF + 255) / 256, 256>>>();
    k_pass2<<<dim3(NPB2, NCH2), TPB2>>>(x);
    k_squash2<<<(NPOS * FF + 255) / 256, 256>>>(out);
}

// round 3
// speedup vs baseline: 1.7208x; 1.7208x over previous
#include <cuda_runtime.h>
#include <math.h>
#include <stdint.h>

#define HIN     14
#define WIN     14
#define HO      12
#define WO      12
#define BATCH   4
#define FIN     32
#define DIN     8
#define FF      32
#define CCAP    288
#define DOUT    16
#define NPOS    (BATCH*HO*WO)   // 576

// pass1: 12 warps, 4 pos/warp -> 48 pos/CTA; 12 c-chunks of 24; grid 12x12=144
#define TPB1    384
#define POSB1   48
#define NPB1    (NPOS/POSB1)    // 12
#define NCH1    12
#define CPC1    (CCAP/NCH1)     // 24

// pass2: 12 warps, 2 pos/warp -> 24 pos/CTA; 6 c-chunks of 48; grid 24x6=144
#define TPB2    384
#define POSB2   24
#define NPB2    (NPOS/POSB2)    // 24
#define NCH2    6
#define CPC2    (CCAP/NCH2)     // 48

typedef unsigned long long u64;

// ---------------- scratch (static device globals) ---------------------------
// Wtp[c][i(8)][p(8)][f(32)] : f32x2 pair (W[f,c,p,i], W[f,c,p+8,i])
__device__ float2 g_Wtp[(size_t)CCAP*8*8*32];                 // 4.7 MB
__device__ float2 g_S1p[(size_t)NCH1*NPOS*FF*8];              // pass1 partials (packed pairs)
__device__ float2 g_out1p[(size_t)NPOS*FF*8];                 // squash(iter1), packed pairs
__device__ float2 g_centp[(size_t)NCH2*NPOS*FF*8];            // pass2 partial centroids

__device__ __constant__ int c_koff[9] = {0, 256, 512, 3584, 3840, 4096, 7168, 7424, 7680};

// ---------------- f32x2 helpers ---------------------------------------------
__device__ __forceinline__ u64 pk(float lo, float hi) {
    u64 r; asm("mov.b64 %0,{%1,%2};" : "=l"(r) : "f"(lo), "f"(hi)); return r;
}
__device__ __forceinline__ void upk(u64 v, float& a, float& b) {
    asm("mov.b64 {%0,%1},%2;" : "=f"(a), "=f"(b) : "l"(v));
}
__device__ __forceinline__ u64 fma2(u64 a, u64 b, u64 c) {
    u64 d; asm("fma.rn.f32x2 %0,%1,%2,%3;" : "=l"(d) : "l"(a), "l"(b), "l"(c)); return d;
}

// ---------------- cp.async helpers -------------------------------------------
__device__ __forceinline__ void cp16(uint32_t saddr, const void* gaddr) {
    asm volatile("cp.async.cg.shared.global [%0], [%1], 16;" :: "r"(saddr), "l"(gaddr));
}
// copy one 16KB W tile (c) into a smem stage; 1024 x 16B chunks
template<int TPB>
__device__ __forceinline__ void stage_copy(u64* sdst, const float2* gsrc, int tid) {
    uint32_t s = (uint32_t)__cvta_generic_to_shared(sdst);
    const char* g = (const char*)gsrc;
    for (int k = tid; k < 1024; k += TPB) cp16(s + k * 16, g + (size_t)k * 16);
    asm volatile("cp.async.commit_group;");
}
__device__ __forceinline__ void wait_all_cp() {
    asm volatile("cp.async.wait_group 0;");
}

// ---------------- W transform: W[f][c][o][i] -> Wtp[c][i][p][f] pairs --------
__global__ void k_transpose(const float* __restrict__ W) {
    int tid = blockIdx.x * blockDim.x + threadIdx.x;
    if (tid >= CCAP * 8 * 32) return;
    int f = tid & 31;
    int r = tid >> 5;
    int p = r & 7;
    int c = r >> 3;
    const float* row0 = W + (((size_t)f * CCAP + c) * DOUT + p) * DIN;
    const float* row8 = W + (((size_t)f * CCAP + c) * DOUT + p + 8) * DIN;
    float4 a0 = ((const float4*)row0)[0], a1 = ((const float4*)row0)[1];
    float4 b0 = ((const float4*)row8)[0], b1 = ((const float4*)row8)[1];
    float a[8] = {a0.x,a0.y,a0.z,a0.w,a1.x,a1.y,a1.z,a1.w};
    float b[8] = {b0.x,b0.y,b0.z,b0.w,b1.x,b1.y,b1.z,b1.w};
    #pragma unroll
    for (int i = 0; i < 8; ++i)
        g_Wtp[(((size_t)c * 8 + i) * 8 + p) * 32 + f] = make_float2(a[i], b[i]);
}

__device__ __forceinline__ const float* pos_base(const float* x, int pos) {
    int b = pos / (HO * WO);
    int r = pos % (HO * WO);
    int h = r / WO;
    int w = r % WO;
    return x + (((size_t)(b * HIN + h) * WIN) + w) * (FIN * DIN);
}

// ---------------- pass 1: partial sum over c of preds (4 pos/warp) ----------
__global__ void __launch_bounds__(TPB1, 1) k_pass1(const float* __restrict__ x) {
    __shared__ u64 sW[2][8][8][32];   // 2 stages x 16KB
    int tid  = threadIdx.x;
    int lane = tid & 31;
    int w    = tid >> 5;
    int pos0 = blockIdx.x * POSB1 + w * 4;
    int cch  = blockIdx.y;
    int cbeg = cch * CPC1;

    const float* xb[4];
    #pragma unroll
    for (int q = 0; q < 4; ++q) xb[q] = pos_base(x, pos0 + q);

    u64 acc[4][8];
    #pragma unroll
    for (int q = 0; q < 4; ++q)
        #pragma unroll
        for (int p = 0; p < 8; ++p) acc[q][p] = 0ULL;

    stage_copy<TPB1>(&sW[0][0][0][0], g_Wtp + (size_t)cbeg * 2048, tid);

    for (int ci = 0; ci < CPC1; ++ci) {
        wait_all_cp();
        __syncthreads();
        if (ci + 1 < CPC1)
            stage_copy<TPB1>(&sW[(ci + 1) & 1][0][0][0],
                             g_Wtp + (size_t)(cbeg + ci + 1) * 2048, tid);

        int c   = cbeg + ci;
        int off = c_koff[c >> 5] + (c & 31) * DIN;
        float xs[4][8];
        #pragma unroll
        for (int q = 0; q < 4; ++q) {
            float4 v0 = ((const float4*)(xb[q] + off))[0];
            float4 v1 = ((const float4*)(xb[q] + off))[1];
            xs[q][0]=v0.x; xs[q][1]=v0.y; xs[q][2]=v0.z; xs[q][3]=v0.w;
            xs[q][4]=v1.x; xs[q][5]=v1.y; xs[q][6]=v1.z; xs[q][7]=v1.w;
        }
        const u64* wb = &sW[ci & 1][0][0][0];
        #pragma unroll
        for (int i = 0; i < 8; ++i) {
            u64 xd0 = pk(xs[0][i], xs[0][i]);
            u64 xd1 = pk(xs[1][i], xs[1][i]);
            u64 xd2 = pk(xs[2][i], xs[2][i]);
            u64 xd3 = pk(xs[3][i], xs[3][i]);
            #pragma unroll
            for (int p = 0; p < 8; ++p) {
                u64 wv = wb[(i * 8 + p) * 32 + lane];
                acc[0][p] = fma2(wv, xd0, acc[0][p]);
                acc[1][p] = fma2(wv, xd1, acc[1][p]);
                acc[2][p] = fma2(wv, xd2, acc[2][p]);
                acc[3][p] = fma2(wv, xd3, acc[3][p]);
            }
        }
    }

    #pragma unroll
    for (int q = 0; q < 4; ++q) {
        u64* d = (u64*)g_S1p + (((size_t)cch * NPOS + pos0 + q) * FF + lane) * 8;
        #pragma unroll
        for (int p = 0; p < 8; ++p) d[p] = acc[q][p];
    }
}

// ---------------- squash 1: out1p = squash(mean over c), packed pairs --------
__global__ void k_squash1() {
    int t = blockIdx.x * blockDim.x + threadIdx.x;   // (pos,f)
    if (t >= NPOS * FF) return;
    float sx[8], sy[8];
    #pragma unroll
    for (int p = 0; p < 8; ++p) { sx[p] = 0.f; sy[p] = 0.f; }
    for (int ch = 0; ch < NCH1; ++ch) {
        const float2* s = g_S1p + ((size_t)ch * NPOS * FF + t) * 8;
        #pragma unroll
        for (int p = 0; p < 8; ++p) { float2 v = s[p]; sx[p] += v.x; sy[p] += v.y; }
    }
    float sn = 0.f;
    #pragma unroll
    for (int p = 0; p < 8; ++p) {
        sx[p] *= (1.f / 32.f); sy[p] *= (1.f / 32.f);
        sn += sx[p] * sx[p] + sy[p] * sy[p];
    }
    float sc = (sn / (1.f + sn)) / sqrtf(sn + 1e-7f);
    float2* d = g_out1p + (size_t)t * 8;
    #pragma unroll
    for (int p = 0; p < 8; ++p) d[p] = make_float2(sx[p] * sc, sy[p] * sc);
}

// ---------------- pass 2: fused agreement/softmax(F)/centroid ----------------
__global__ void __launch_bounds__(TPB2, 1) k_pass2(const float* __restrict__ x) {
    __shared__ u64 sW[2][8][8][32];
    int tid  = threadIdx.x;
    int lane = tid & 31;
    int w    = tid >> 5;
    int pos0 = blockIdx.x * POSB2 + w * 2;
    int pos1 = pos0 + 1;
    int cch  = blockIdx.y;
    int cbeg = cch * CPC2;

    const float* xb0 = pos_base(x, pos0);
    const float* xb1 = pos_base(x, pos1);

    // packed out1 for (pos, f=lane)
    u64 o1a[8], o1b[8];
    {
        const u64* q0 = (const u64*)g_out1p + (((size_t)pos0 * FF) + lane) * 8;
        const u64* q1 = (const u64*)g_out1p + (((size_t)pos1 * FF) + lane) * 8;
        #pragma unroll
        for (int p = 0; p < 8; ++p) { o1a[p] = q0[p]; o1b[p] = q1[p]; }
    }

    u64 ce0[8], ce1[8];
    #pragma unroll
    for (int p = 0; p < 8; ++p) { ce0[p] = 0ULL; ce1[p] = 0ULL; }

    stage_copy<TPB2>(&sW[0][0][0][0], g_Wtp + (size_t)cbeg * 2048, tid);

    for (int ci = 0; ci < CPC2; ++ci) {
        wait_all_cp();
        __syncthreads();
        if (ci + 1 < CPC2)
            stage_copy<TPB2>(&sW[(ci + 1) & 1][0][0][0],
                             g_Wtp + (size_t)(cbeg + ci + 1) * 2048, tid);

        int c   = cbeg + ci;
        int off = c_koff[c >> 5] + (c & 31) * DIN;
        float4 v0 = ((const float4*)(xb0 + off))[0];
        float4 v1 = ((const float4*)(xb0 + off))[1];
        float4 u0 = ((const float4*)(xb1 + off))[0];
        float4 u1 = ((const float4*)(xb1 + off))[1];
        float xs0[8] = {v0.x,v0.y,v0.z,v0.w,v1.x,v1.y,v1.z,v1.w};
        float xs1[8] = {u0.x,u0.y,u0.z,u0.w,u1.x,u1.y,u1.z,u1.w};

        u64 pr0[8], pr1[8];
        #pragma unroll
        for (int p = 0; p < 8; ++p) { pr0[p] = 0ULL; pr1[p] = 0ULL; }

        const u64* wb = &sW[ci & 1][0][0][0];
        #pragma unroll
        for (int i = 0; i < 8; ++i) {
            u64 xd0 = pk(xs0[i], xs0[i]);
            u64 xd1 = pk(xs1[i], xs1[i]);
            #pragma unroll
            for (int p = 0; p < 8; ++p) {
                u64 wv = wb[(i * 8 + p) * 32 + lane];
                pr0[p] = fma2(wv, xd0, pr0[p]);
                pr1[p] = fma2(wv, xd1, pr1[p]);
            }
        }

        // agreement dots (packed), then horizontal add
        u64 acc0 = 0ULL, acc1 = 0ULL;
        #pragma unroll
        for (int p = 0; p < 8; ++p) {
            acc0 = fma2(pr0[p], o1a[p], acc0);
            acc1 = fma2(pr1[p], o1b[p], acc1);
        }
        float a0l, a0h, a1l, a1h;
        upk(acc0, a0l, a0h);
        upk(acc1, a1l, a1h);
        // no max-subtraction: |agreement| is O(1), exp safe in fp32
        float e0 = __expf(a0l + a0h);
        float e1 = __expf(a1l + a1h);

        float s0 = e0, s1 = e1;
        #pragma unroll
        for (int d = 16; d > 0; d >>= 1) {
            s0 += __shfl_xor_sync(0xffffffffu, s0, d);
            s1 += __shfl_xor_sync(0xffffffffu, s1, d);
        }
        float cc0 = __fdividef(e0, s0);
        float cc1 = __fdividef(e1, s1);
        u64 cd0 = pk(cc0, cc0);
        u64 cd1 = pk(cc1, cc1);

        #pragma unroll
        for (int p = 0; p < 8; ++p) {
            ce0[p] = fma2(pr0[p], cd0, ce0[p]);
            ce1[p] = fma2(pr1[p], cd1, ce1[p]);
        }
    }

    u64* d0 = (u64*)g_centp + (((size_t)cch * NPOS + pos0) * FF + lane) * 8;
    u64* d1 = (u64*)g_centp + (((size_t)cch * NPOS + pos1) * FF + lane) * 8;
    #pragma unroll
    for (int p = 0; p < 8; ++p) { d0[p] = ce0[p]; d1[p] = ce1[p]; }
}

// ---------------- squash 2: final output (unpack pairs) ----------------------
__global__ void k_squash2(float* __restrict__ out) {
    int t = blockIdx.x * blockDim.x + threadIdx.x;   // (pos,f)
    if (t >= NPOS * FF) return;
    float sx[8], sy[8];
    #pragma unroll
    for (int p = 0; p < 8; ++p) { sx[p] = 0.f; sy[p] = 0.f; }
    for (int ch = 0; ch < NCH2; ++ch) {
        const float2* s = g_centp + ((size_t)ch * NPOS * FF + t) * 8;
        #pragma unroll
        for (int p = 0; p < 8; ++p) { float2 v = s[p]; sx[p] += v.x; sy[p] += v.y; }
    }
    float sn = 0.f;
    #pragma unroll
    for (int p = 0; p < 8; ++p) sn += sx[p] * sx[p] + sy[p] * sy[p];
    float sc = (sn / (1.f + sn)) / sqrtf(sn + 1e-7f);
    float* d = out + (size_t)t * DOUT;
    #pragma unroll
    for (int p = 0; p < 8; ++p) { d[p] = sx[p] * sc; d[p + 8] = sy[p] * sc; }
}

// -----------------------------------------------------------------------------
extern "C" void kernel_launch(void* const* d_in, const int* in_sizes, int n_in,
                              void* d_out, int out_size) {
    const float* x = (const float*)d_in[0];
    const float* W = (const float*)d_in[1];
    if (n_in >= 2 && in_sizes[0] == (int)((size_t)FF * CCAP * DOUT * DIN)) {
        const float* t = x; x = W; W = t;
    }
    float* out = (float*)d_out;

    k_transpose<<<(CCAP * 8 * 32 + 255) / 256, 256>>>(W);
    k_pass1<<<dim3(NPB1, NCH1), TPB1>>>(x);
    k_squash1<<<(NPOS * FF + 255) / 256, 256>>>();
    k_pass2<<<dim3(NPB2, NCH2), TPB2>>>(x);
    k_squash2<<<(NPOS * FF + 255) / 256, 256>>>(out);
}

// round 4
// speedup vs baseline: 1.8382x; 1.0683x over previous
#include <cuda_runtime.h>
#include <math.h>
#include <stdint.h>

#define HIN     14
#define WIN     14
#define HO      12
#define WO      12
#define BATCH   4
#define FIN     32
#define DIN     8
#define FF      32
#define CCAP    288
#define DOUT    16
#define NPOS    (BATCH*HO*WO)   // 576

// pass1: 12 warps, 4 pos/warp -> 48 pos/CTA; 12 c-chunks of 24; grid 12x12=144
#define TPB1    384
#define POSB1   48
#define NPB1    (NPOS/POSB1)    // 12
#define NCH1    12
#define CPC1    (CCAP/NCH1)     // 24

// pass2: 12 warps, 3 pos/warp -> 36 pos/CTA; 9 c-chunks of 32; grid 16x9=144
#define TPB2    384
#define POSB2   36
#define NPB2    (NPOS/POSB2)    // 16
#define NCH2    9
#define CPC2    (CCAP/NCH2)     // 32

typedef unsigned long long u64;

// ---------------- scratch (static device globals) ---------------------------
// Wtp[c][i(8)][p(8)][f(32)] : f32x2 pair (W[f,c,p,i], W[f,c,p+8,i])
__device__ float2 g_Wtp[(size_t)CCAP*8*8*32];                 // 4.7 MB
__device__ float2 g_S1p[(size_t)NCH1*NPOS*FF*8];              // pass1 partials
__device__ float2 g_out1p[(size_t)NPOS*FF*8];                 // squash(iter1)
__device__ float2 g_centp[(size_t)12*NPOS*FF*8];              // pass2 partial centroids

__device__ __constant__ int c_koff[9] = {0, 256, 512, 3584, 3840, 4096, 7168, 7424, 7680};

// ---------------- f32x2 helpers ---------------------------------------------
__device__ __forceinline__ u64 pk(float lo, float hi) {
    u64 r; asm("mov.b64 %0,{%1,%2};" : "=l"(r) : "f"(lo), "f"(hi)); return r;
}
__device__ __forceinline__ void upk(u64 v, float& a, float& b) {
    asm("mov.b64 {%0,%1},%2;" : "=f"(a), "=f"(b) : "l"(v));
}
__device__ __forceinline__ u64 fma2(u64 a, u64 b, u64 c) {
    u64 d; asm("fma.rn.f32x2 %0,%1,%2,%3;" : "=l"(d) : "l"(a), "l"(b), "l"(c)); return d;
}

// ---------------- cp.async helpers -------------------------------------------
__device__ __forceinline__ void cp16(uint32_t saddr, const void* gaddr) {
    asm volatile("cp.async.cg.shared.global [%0], [%1], 16;" :: "r"(saddr), "l"(gaddr));
}
// copy one 16KB W tile into a smem stage; 1024 x 16B chunks; commits a group
template<int TPB>
__device__ __forceinline__ void stage_copy(u64* sdst, const float2* gsrc, int tid) {
    uint32_t s = (uint32_t)__cvta_generic_to_shared(sdst);
    const char* g = (const char*)gsrc;
    #pragma unroll
    for (int k = 0; k < 1024 / TPB + (1024 % TPB ? 1 : 0); ++k) {
        int idx = tid + k * TPB;
        if (idx < 1024) cp16(s + idx * 16, g + (size_t)idx * 16);
    }
    asm volatile("cp.async.commit_group;");
}
__device__ __forceinline__ void wait_cp1() {   // allow 1 group outstanding
    asm volatile("cp.async.wait_group 1;");
}

// ---------------- W transform: W[f][c][o][i] -> Wtp[c][i][p][f] pairs --------
__global__ void k_transpose(const float* __restrict__ W) {
    int tid = blockIdx.x * blockDim.x + threadIdx.x;
    if (tid >= CCAP * 8 * 32) return;
    int f = tid & 31;
    int r = tid >> 5;
    int p = r & 7;
    int c = r >> 3;
    const float* row0 = W + (((size_t)f * CCAP + c) * DOUT + p) * DIN;
    const float* row8 = W + (((size_t)f * CCAP + c) * DOUT + p + 8) * DIN;
    float4 a0 = ((const float4*)row0)[0], a1 = ((const float4*)row0)[1];
    float4 b0 = ((const float4*)row8)[0], b1 = ((const float4*)row8)[1];
    float a[8] = {a0.x,a0.y,a0.z,a0.w,a1.x,a1.y,a1.z,a1.w};
    float b[8] = {b0.x,b0.y,b0.z,b0.w,b1.x,b1.y,b1.z,b1.w};
    #pragma unroll
    for (int i = 0; i < 8; ++i)
        g_Wtp[(((size_t)c * 8 + i) * 8 + p) * 32 + f] = make_float2(a[i], b[i]);
}

__device__ __forceinline__ const float* pos_base(const float* x, int pos) {
    int b = pos / (HO * WO);
    int r = pos % (HO * WO);
    int h = r / WO;
    int w = r % WO;
    return x + (((size_t)(b * HIN + h) * WIN) + w) * (FIN * DIN);
}

// ---------------- pass 1: partial sum over c of preds (4 pos/warp) ----------
__global__ void __launch_bounds__(TPB1, 1) k_pass1(const float* __restrict__ x) {
    __shared__ u64 sW[3][8][8][32];   // 3 stages x 16KB
    int tid  = threadIdx.x;
    int lane = tid & 31;
    int w    = tid >> 5;
    int pos0 = blockIdx.x * POSB1 + w * 4;
    int cch  = blockIdx.y;
    int cbeg = cch * CPC1;

    const float* xb[4];
    #pragma unroll
    for (int q = 0; q < 4; ++q) xb[q] = pos_base(x, pos0 + q);

    u64 acc[4][8];
    #pragma unroll
    for (int q = 0; q < 4; ++q)
        #pragma unroll
        for (int p = 0; p < 8; ++p) acc[q][p] = 0ULL;

    stage_copy<TPB1>(&sW[0][0][0][0], g_Wtp + (size_t)cbeg * 2048, tid);
    stage_copy<TPB1>(&sW[1][0][0][0], g_Wtp + (size_t)(cbeg + 1) * 2048, tid);

    for (int ci = 0; ci < CPC1; ++ci) {
        wait_cp1();
        __syncthreads();
        if (ci + 2 < CPC1)
            stage_copy<TPB1>(&sW[(ci + 2) % 3][0][0][0],
                             g_Wtp + (size_t)(cbeg + ci + 2) * 2048, tid);

        int c   = cbeg + ci;
        int off = c_koff[c >> 5] + (c & 31) * DIN;
        float xs[4][8];
        #pragma unroll
        for (int q = 0; q < 4; ++q) {
            float4 v0 = ((const float4*)(xb[q] + off))[0];
            float4 v1 = ((const float4*)(xb[q] + off))[1];
            xs[q][0]=v0.x; xs[q][1]=v0.y; xs[q][2]=v0.z; xs[q][3]=v0.w;
            xs[q][4]=v1.x; xs[q][5]=v1.y; xs[q][6]=v1.z; xs[q][7]=v1.w;
        }
        const u64* wb = &sW[ci % 3][0][0][0];
        #pragma unroll
        for (int i = 0; i < 8; ++i) {
            u64 xd0 = pk(xs[0][i], xs[0][i]);
            u64 xd1 = pk(xs[1][i], xs[1][i]);
            u64 xd2 = pk(xs[2][i], xs[2][i]);
            u64 xd3 = pk(xs[3][i], xs[3][i]);
            #pragma unroll
            for (int p = 0; p < 8; ++p) {
                u64 wv = wb[(i * 8 + p) * 32 + lane];
                acc[0][p] = fma2(wv, xd0, acc[0][p]);
                acc[1][p] = fma2(wv, xd1, acc[1][p]);
                acc[2][p] = fma2(wv, xd2, acc[2][p]);
                acc[3][p] = fma2(wv, xd3, acc[3][p]);
            }
        }
    }

    #pragma unroll
    for (int q = 0; q < 4; ++q) {
        u64* d = (u64*)g_S1p + (((size_t)cch * NPOS + pos0 + q) * FF + lane) * 8;
        #pragma unroll
        for (int p = 0; p < 8; ++p) d[p] = acc[q][p];
    }
}

// ---------------- squash 1 ---------------------------------------------------
__global__ void k_squash1() {
    int t = blockIdx.x * blockDim.x + threadIdx.x;   // (pos,f)
    if (t >= NPOS * FF) return;
    float sx[8], sy[8];
    #pragma unroll
    for (int p = 0; p < 8; ++p) { sx[p] = 0.f; sy[p] = 0.f; }
    for (int ch = 0; ch < NCH1; ++ch) {
        const float2* s = g_S1p + ((size_t)ch * NPOS * FF + t) * 8;
        #pragma unroll
        for (int p = 0; p < 8; ++p) { float2 v = s[p]; sx[p] += v.x; sy[p] += v.y; }
    }
    float sn = 0.f;
    #pragma unroll
    for (int p = 0; p < 8; ++p) {
        sx[p] *= (1.f / 32.f); sy[p] *= (1.f / 32.f);
        sn += sx[p] * sx[p] + sy[p] * sy[p];
    }
    float sc = (sn / (1.f + sn)) / sqrtf(sn + 1e-7f);
    float2* d = g_out1p + (size_t)t * 8;
    #pragma unroll
    for (int p = 0; p < 8; ++p) d[p] = make_float2(sx[p] * sc, sy[p] * sc);
}

// ---------------- pass 2: fused agreement/softmax(F)/centroid (3 pos/warp) --
__global__ void __launch_bounds__(TPB2, 1) k_pass2(const float* __restrict__ x) {
    __shared__ u64 sW[3][8][8][32];   // 3 stages x 16KB
    int tid  = threadIdx.x;
    int lane = tid & 31;
    int w    = tid >> 5;
    int pos0 = blockIdx.x * POSB2 + w * 3;
    int cch  = blockIdx.y;
    int cbeg = cch * CPC2;

    const float* xb[3];
    #pragma unroll
    for (int q = 0; q < 3; ++q) xb[q] = pos_base(x, pos0 + q);

    // packed out1 for (pos, f=lane)
    u64 o1[3][8];
    #pragma unroll
    for (int q = 0; q < 3; ++q) {
        const u64* s = (const u64*)g_out1p + (((size_t)(pos0 + q) * FF) + lane) * 8;
        #pragma unroll
        for (int p = 0; p < 8; ++p) o1[q][p] = s[p];
    }

    u64 ce[3][8];
    #pragma unroll
    for (int q = 0; q < 3; ++q)
        #pragma unroll
        for (int p = 0; p < 8; ++p) ce[q][p] = 0ULL;

    stage_copy<TPB2>(&sW[0][0][0][0], g_Wtp + (size_t)cbeg * 2048, tid);
    stage_copy<TPB2>(&sW[1][0][0][0], g_Wtp + (size_t)(cbeg + 1) * 2048, tid);

    for (int ci = 0; ci < CPC2; ++ci) {
        wait_cp1();
        __syncthreads();
        if (ci + 2 < CPC2)
            stage_copy<TPB2>(&sW[(ci + 2) % 3][0][0][0],
                             g_Wtp + (size_t)(cbeg + ci + 2) * 2048, tid);

        int c   = cbeg + ci;
        int off = c_koff[c >> 5] + (c & 31) * DIN;
        float xs[3][8];
        #pragma unroll
        for (int q = 0; q < 3; ++q) {
            float4 v0 = ((const float4*)(xb[q] + off))[0];
            float4 v1 = ((const float4*)(xb[q] + off))[1];
            xs[q][0]=v0.x; xs[q][1]=v0.y; xs[q][2]=v0.z; xs[q][3]=v0.w;
            xs[q][4]=v1.x; xs[q][5]=v1.y; xs[q][6]=v1.z; xs[q][7]=v1.w;
        }

        u64 pr[3][8];
        #pragma unroll
        for (int q = 0; q < 3; ++q)
            #pragma unroll
            for (int p = 0; p < 8; ++p) pr[q][p] = 0ULL;

        const u64* wb = &sW[ci % 3][0][0][0];
        #pragma unroll
        for (int i = 0; i < 8; ++i) {
            u64 xd0 = pk(xs[0][i], xs[0][i]);
            u64 xd1 = pk(xs[1][i], xs[1][i]);
            u64 xd2 = pk(xs[2][i], xs[2][i]);
            #pragma unroll
            for (int p = 0; p < 8; ++p) {
                u64 wv = wb[(i * 8 + p) * 32 + lane];
                pr[0][p] = fma2(wv, xd0, pr[0][p]);
                pr[1][p] = fma2(wv, xd1, pr[1][p]);
                pr[2][p] = fma2(wv, xd2, pr[2][p]);
            }
        }

        // agreement dots (packed), then horizontal add; no max-subtraction
        float e0, e1, e2;
        {
            u64 a0 = 0ULL, a1 = 0ULL, a2 = 0ULL;
            #pragma unroll
            for (int p = 0; p < 8; ++p) {
                a0 = fma2(pr[0][p], o1[0][p], a0);
                a1 = fma2(pr[1][p], o1[1][p], a1);
                a2 = fma2(pr[2][p], o1[2][p], a2);
            }
            float l, h;
            upk(a0, l, h); e0 = __expf(l + h);
            upk(a1, l, h); e1 = __expf(l + h);
            upk(a2, l, h); e2 = __expf(l + h);
        }

        float s0 = e0, s1 = e1, s2 = e2;
        #pragma unroll
        for (int d = 16; d > 0; d >>= 1) {
            s0 += __shfl_xor_sync(0xffffffffu, s0, d);
            s1 += __shfl_xor_sync(0xffffffffu, s1, d);
            s2 += __shfl_xor_sync(0xffffffffu, s2, d);
        }
        u64 cd0 = pk(__fdividef(e0, s0), __fdividef(e0, s0));
        u64 cd1 = pk(__fdividef(e1, s1), __fdividef(e1, s1));
        u64 cd2 = pk(__fdividef(e2, s2), __fdividef(e2, s2));

        #pragma unroll
        for (int p = 0; p < 8; ++p) {
            ce[0][p] = fma2(pr[0][p], cd0, ce[0][p]);
            ce[1][p] = fma2(pr[1][p], cd1, ce[1][p]);
            ce[2][p] = fma2(pr[2][p], cd2, ce[2][p]);
        }
    }

    #pragma unroll
    for (int q = 0; q < 3; ++q) {
        u64* d = (u64*)g_centp + (((size_t)cch * NPOS + pos0 + q) * FF + lane) * 8;
        #pragma unroll
        for (int p = 0; p < 8; ++p) d[p] = ce[q][p];
    }
}

// ---------------- squash 2: final output ------------------------------------
__global__ void k_squash2(float* __restrict__ out) {
    int t = blockIdx.x * blockDim.x + threadIdx.x;   // (pos,f)
    if (t >= NPOS * FF) return;
    float sx[8], sy[8];
    #pragma unroll
    for (int p = 0; p < 8; ++p) { sx[p] = 0.f; sy[p] = 0.f; }
    for (int ch = 0; ch < NCH2; ++ch) {
        const float2* s = g_centp + ((size_t)ch * NPOS * FF + t) * 8;
        #pragma unroll
        for (int p = 0; p < 8; ++p) { float2 v = s[p]; sx[p] += v.x; sy[p] += v.y; }
    }
    float sn = 0.f;
    #pragma unroll
    for (int p = 0; p < 8; ++p) sn += sx[p] * sx[p] + sy[p] * sy[p];
    float sc = (sn / (1.f + sn)) / sqrtf(sn + 1e-7f);
    float* d = out + (size_t)t * DOUT;
    #pragma unroll
    for (int p = 0; p < 8; ++p) { d[p] = sx[p] * sc; d[p + 8] = sy[p] * sc; }
}

// -----------------------------------------------------------------------------
extern "C" void kernel_launch(void* const* d_in, const int* in_sizes, int n_in,
                              void* d_out, int out_size) {
    const float* x = (const float*)d_in[0];
    const float* W = (const float*)d_in[1];
    if (n_in >= 2 && in_sizes[0] == (int)((size_t)FF * CCAP * DOUT * DIN)) {
        const float* t = x; x = W; W = t;
    }
    float* out = (float*)d_out;

    k_transpose<<<(CCAP * 8 * 32 + 255) / 256, 256>>>(W);
    k_pass1<<<dim3(NPB1, NCH1), TPB1>>>(x);
    k_squash1<<<(NPOS * FF + 255) / 256, 256>>>();
    k_pass2<<<dim3(NPB2, NCH2), TPB2>>>(x);
    k_squash2<<<(NPOS * FF + 255) / 256, 256>>>(out);
}

// round 5
// speedup vs baseline: 1.9307x; 1.0503x over previous
#include <cuda_runtime.h>
#include <math.h>
#include <stdint.h>

#define HIN     14
#define WIN     14
#define HO      12
#define WO      12
#define BATCH   4
#define FIN     32
#define DIN     8
#define FF      32
#define CCAP    288
#define DOUT    16
#define NPOS    (BATCH*HO*WO)   // 576

// pass1: 12 warps, 4 pos/warp -> 48 pos/CTA; 12 c-chunks of 24; grid 12x12=144
#define TPB1    384
#define POSB1   48
#define NPB1    (NPOS/POSB1)    // 12
#define NCH1    12
#define CPC1    (CCAP/NCH1)     // 24  (6 quartets)

// pass2: 12 warps, 3 pos/warp -> 36 pos/CTA; 9 c-chunks of 32; grid 16x9=144
#define TPB2    384
#define POSB2   36
#define NPB2    (NPOS/POSB2)    // 16
#define NCH2    9
#define CPC2    (CCAP/NCH2)     // 32  (8 quartets)

#define SMEM_BYTES (8 * 2048 * 8)   // 8 stages x 16KB = 128KB

typedef unsigned long long u64;

// ---------------- scratch (static device globals) ---------------------------
__device__ float2 g_Wtp[(size_t)CCAP*8*8*32];                 // [c][i][p][f] f32x2 pairs
__device__ float2 g_S1p[(size_t)NCH1*NPOS*FF*8];              // pass1 partials
__device__ float2 g_out1p[(size_t)NPOS*FF*8];                 // squash(iter1)
__device__ float2 g_centp[(size_t)12*NPOS*FF*8];              // pass2 partial centroids

__device__ __constant__ int c_koff[9] = {0, 256, 512, 3584, 3840, 4096, 7168, 7424, 7680};

// ---------------- f32x2 helpers ---------------------------------------------
__device__ __forceinline__ u64 pk(float lo, float hi) {
    u64 r; asm("mov.b64 %0,{%1,%2};" : "=l"(r) : "f"(lo), "f"(hi)); return r;
}
__device__ __forceinline__ void upk(u64 v, float& a, float& b) {
    asm("mov.b64 {%0,%1},%2;" : "=f"(a), "=f"(b) : "l"(v));
}
__device__ __forceinline__ u64 fma2(u64 a, u64 b, u64 c) {
    u64 d; asm("fma.rn.f32x2 %0,%1,%2,%3;" : "=l"(d) : "l"(a), "l"(b), "l"(c)); return d;
}

// ---------------- cp.async helpers -------------------------------------------
__device__ __forceinline__ void cp16(uint32_t saddr, const void* gaddr) {
    asm volatile("cp.async.cg.shared.global [%0], [%1], 16;" :: "r"(saddr), "l"(gaddr));
}
// copy one 16KB W tile into smem stage; commits one group
template<int TPB>
__device__ __forceinline__ void stage_copy(u64* sdst, const float2* gsrc, int tid) {
    uint32_t s = (uint32_t)__cvta_generic_to_shared(sdst);
    const char* g = (const char*)gsrc;
    #pragma unroll
    for (int k = 0; k < (1024 + TPB - 1) / TPB; ++k) {
        int idx = tid + k * TPB;
        if (idx < 1024) cp16(s + idx * 16, g + (size_t)idx * 16);
    }
    asm volatile("cp.async.commit_group;");
}
template<int N>
__device__ __forceinline__ void wait_cp() {
    asm volatile("cp.async.wait_group %0;" :: "n"(N));
}

// ---------------- W transform: W[f][c][o][i] -> Wtp[c][i][p][f] pairs --------
__global__ void k_transpose(const float* __restrict__ W) {
    int tid = blockIdx.x * blockDim.x + threadIdx.x;
    if (tid >= CCAP * 8 * 32) return;
    int f = tid & 31;
    int r = tid >> 5;
    int p = r & 7;
    int c = r >> 3;
    const float* row0 = W + (((size_t)f * CCAP + c) * DOUT + p) * DIN;
    const float* row8 = W + (((size_t)f * CCAP + c) * DOUT + p + 8) * DIN;
    float4 a0 = ((const float4*)row0)[0], a1 = ((const float4*)row0)[1];
    float4 b0 = ((const float4*)row8)[0], b1 = ((const float4*)row8)[1];
    float a[8] = {a0.x,a0.y,a0.z,a0.w,a1.x,a1.y,a1.z,a1.w};
    float b[8] = {b0.x,b0.y,b0.z,b0.w,b1.x,b1.y,b1.z,b1.w};
    #pragma unroll
    for (int i = 0; i < 8; ++i)
        g_Wtp[(((size_t)c * 8 + i) * 8 + p) * 32 + f] = make_float2(a[i], b[i]);
}

__device__ __forceinline__ const float* pos_base(const float* x, int pos) {
    int b = pos / (HO * WO);
    int r = pos % (HO * WO);
    int h = r / WO;
    int w = r % WO;
    return x + (((size_t)(b * HIN + h) * WIN) + w) * (FIN * DIN);
}

// ---------------- pass 1: partial sum over c of preds (4 pos/warp) ----------
// 8-stage pipeline, quartet barriers, warp-rotated c order within quartet.
__global__ void __launch_bounds__(TPB1, 1) k_pass1(const float* __restrict__ x) {
    extern __shared__ u64 sW[];   // 8 stages x 2048 u64
    int tid  = threadIdx.x;
    int lane = tid & 31;
    int w    = tid >> 5;
    int pos0 = blockIdx.x * POSB1 + w * 4;
    int cch  = blockIdx.y;
    int cbeg = cch * CPC1;
    const int NT = CPC1 / 4;   // 6 quartets

    const float* xb[4];
    #pragma unroll
    for (int q = 0; q < 4; ++q) xb[q] = pos_base(x, pos0 + q);

    u64 acc[4][8];
    #pragma unroll
    for (int q = 0; q < 4; ++q)
        #pragma unroll
        for (int p = 0; p < 8; ++p) acc[q][p] = 0ULL;

    // prologue: quartets 0 and 1
    #pragma unroll
    for (int j = 0; j < 4; ++j)
        stage_copy<TPB1>(sW + (size_t)j * 2048, g_Wtp + (size_t)(cbeg + j) * 2048, tid);
    #pragma unroll
    for (int j = 0; j < 4; ++j)
        stage_copy<TPB1>(sW + (size_t)(4 + j) * 2048, g_Wtp + (size_t)(cbeg + 4 + j) * 2048, tid);

    for (int t = 0; t < NT; ++t) {
        if (t + 1 < NT) wait_cp<4>(); else wait_cp<0>();
        __syncthreads();
        int sset = (t & 1) * 4;
        int qbeg = cbeg + t * 4;

        #pragma unroll
        for (int k = 0; k < 4; ++k) {
            int j = (w + k) & 3;          // rotated order per warp
            int c = qbeg + j;
            int off = c_koff[c >> 5] + (c & 31) * DIN;
            float xs[4][8];
            #pragma unroll
            for (int q = 0; q < 4; ++q) {
                float4 v0 = ((const float4*)(xb[q] + off))[0];
                float4 v1 = ((const float4*)(xb[q] + off))[1];
                xs[q][0]=v0.x; xs[q][1]=v0.y; xs[q][2]=v0.z; xs[q][3]=v0.w;
                xs[q][4]=v1.x; xs[q][5]=v1.y; xs[q][6]=v1.z; xs[q][7]=v1.w;
            }
            const u64* wb = sW + (size_t)(sset + j) * 2048;
            #pragma unroll
            for (int i = 0; i < 8; ++i) {
                u64 xd0 = pk(xs[0][i], xs[0][i]);
                u64 xd1 = pk(xs[1][i], xs[1][i]);
                u64 xd2 = pk(xs[2][i], xs[2][i]);
                u64 xd3 = pk(xs[3][i], xs[3][i]);
                #pragma unroll
                for (int p = 0; p < 8; ++p) {
                    u64 wv = wb[(i * 8 + p) * 32 + lane];
                    acc[0][p] = fma2(wv, xd0, acc[0][p]);
                    acc[1][p] = fma2(wv, xd1, acc[1][p]);
                    acc[2][p] = fma2(wv, xd2, acc[2][p]);
                    acc[3][p] = fma2(wv, xd3, acc[3][p]);
                }
            }
        }

        __syncthreads();
        if (t + 2 < NT) {
            #pragma unroll
            for (int j = 0; j < 4; ++j)
                stage_copy<TPB1>(sW + (size_t)(sset + j) * 2048,
                                 g_Wtp + (size_t)(cbeg + (t + 2) * 4 + j) * 2048, tid);
        }
    }

    #pragma unroll
    for (int q = 0; q < 4; ++q) {
        u64* d = (u64*)g_S1p + (((size_t)cch * NPOS + pos0 + q) * FF + lane) * 8;
        #pragma unroll
        for (int p = 0; p < 8; ++p) d[p] = acc[q][p];
    }
}

// ---------------- squash 1 ---------------------------------------------------
__global__ void k_squash1() {
    int t = blockIdx.x * blockDim.x + threadIdx.x;   // (pos,f)
    if (t >= NPOS * FF) return;
    float sx[8], sy[8];
    #pragma unroll
    for (int p = 0; p < 8; ++p) { sx[p] = 0.f; sy[p] = 0.f; }
    for (int ch = 0; ch < NCH1; ++ch) {
        const float2* s = g_S1p + ((size_t)ch * NPOS * FF + t) * 8;
        #pragma unroll
        for (int p = 0; p < 8; ++p) { float2 v = s[p]; sx[p] += v.x; sy[p] += v.y; }
    }
    float sn = 0.f;
    #pragma unroll
    for (int p = 0; p < 8; ++p) {
        sx[p] *= (1.f / 32.f); sy[p] *= (1.f / 32.f);
        sn += sx[p] * sx[p] + sy[p] * sy[p];
    }
    float sc = (sn / (1.f + sn)) / sqrtf(sn + 1e-7f);
    float2* d = g_out1p + (size_t)t * 8;
    #pragma unroll
    for (int p = 0; p < 8; ++p) d[p] = make_float2(sx[p] * sc, sy[p] * sc);
}

// ---------------- pass 2: fused agreement/softmax(F)/centroid (3 pos/warp) --
__global__ void __launch_bounds__(TPB2, 1) k_pass2(const float* __restrict__ x) {
    extern __shared__ u64 sW[];   // 8 stages x 2048 u64
    int tid  = threadIdx.x;
    int lane = tid & 31;
    int w    = tid >> 5;
    int pos0 = blockIdx.x * POSB2 + w * 3;
    int cch  = blockIdx.y;
    int cbeg = cch * CPC2;
    const int NT = CPC2 / 4;   // 8 quartets

    const float* xb[3];
    #pragma unroll
    for (int q = 0; q < 3; ++q) xb[q] = pos_base(x, pos0 + q);

    u64 o1[3][8];
    #pragma unroll
    for (int q = 0; q < 3; ++q) {
        const u64* s = (const u64*)g_out1p + (((size_t)(pos0 + q) * FF) + lane) * 8;
        #pragma unroll
        for (int p = 0; p < 8; ++p) o1[q][p] = s[p];
    }

    u64 ce[3][8];
    #pragma unroll
    for (int q = 0; q < 3; ++q)
        #pragma unroll
        for (int p = 0; p < 8; ++p) ce[q][p] = 0ULL;

    #pragma unroll
    for (int j = 0; j < 4; ++j)
        stage_copy<TPB2>(sW + (size_t)j * 2048, g_Wtp + (size_t)(cbeg + j) * 2048, tid);
    #pragma unroll
    for (int j = 0; j < 4; ++j)
        stage_copy<TPB2>(sW + (size_t)(4 + j) * 2048, g_Wtp + (size_t)(cbeg + 4 + j) * 2048, tid);

    for (int t = 0; t < NT; ++t) {
        if (t + 1 < NT) wait_cp<4>(); else wait_cp<0>();
        __syncthreads();
        int sset = (t & 1) * 4;
        int qbeg = cbeg + t * 4;

        #pragma unroll
        for (int k = 0; k < 4; ++k) {
            int j = (w + k) & 3;          // rotated order per warp -> phase mixing
            int c = qbeg + j;
            int off = c_koff[c >> 5] + (c & 31) * DIN;
            float xs[3][8];
            #pragma unroll
            for (int q = 0; q < 3; ++q) {
                float4 v0 = ((const float4*)(xb[q] + off))[0];
                float4 v1 = ((const float4*)(xb[q] + off))[1];
                xs[q][0]=v0.x; xs[q][1]=v0.y; xs[q][2]=v0.z; xs[q][3]=v0.w;
                xs[q][4]=v1.x; xs[q][5]=v1.y; xs[q][6]=v1.z; xs[q][7]=v1.w;
            }

            u64 pr[3][8];
            #pragma unroll
            for (int q = 0; q < 3; ++q)
                #pragma unroll
                for (int p = 0; p < 8; ++p) pr[q][p] = 0ULL;

            const u64* wb = sW + (size_t)(sset + j) * 2048;
            #pragma unroll
            for (int i = 0; i < 8; ++i) {
                u64 xd0 = pk(xs[0][i], xs[0][i]);
                u64 xd1 = pk(xs[1][i], xs[1][i]);
                u64 xd2 = pk(xs[2][i], xs[2][i]);
                #pragma unroll
                for (int p = 0; p < 8; ++p) {
                    u64 wv = wb[(i * 8 + p) * 32 + lane];
                    pr[0][p] = fma2(wv, xd0, pr[0][p]);
                    pr[1][p] = fma2(wv, xd1, pr[1][p]);
                    pr[2][p] = fma2(wv, xd2, pr[2][p]);
                }
            }

            // agreement dots (packed), horizontal add; no max-subtraction
            float e0, e1, e2;
            {
                u64 a0 = 0ULL, a1 = 0ULL, a2 = 0ULL;
                #pragma unroll
                for (int p = 0; p < 8; ++p) {
                    a0 = fma2(pr[0][p], o1[0][p], a0);
                    a1 = fma2(pr[1][p], o1[1][p], a1);
                    a2 = fma2(pr[2][p], o1[2][p], a2);
                }
                float l, h;
                upk(a0, l, h); e0 = __expf(l + h);
                upk(a1, l, h); e1 = __expf(l + h);
                upk(a2, l, h); e2 = __expf(l + h);
            }

            float s0 = e0, s1 = e1, s2 = e2;
            #pragma unroll
            for (int d = 16; d > 0; d >>= 1) {
                s0 += __shfl_xor_sync(0xffffffffu, s0, d);
                s1 += __shfl_xor_sync(0xffffffffu, s1, d);
                s2 += __shfl_xor_sync(0xffffffffu, s2, d);
            }
            float c0 = __fdividef(e0, s0);
            float c1 = __fdividef(e1, s1);
            float c2 = __fdividef(e2, s2);
            u64 cd0 = pk(c0, c0);
            u64 cd1 = pk(c1, c1);
            u64 cd2 = pk(c2, c2);

            #pragma unroll
            for (int p = 0; p < 8; ++p) {
                ce[0][p] = fma2(pr[0][p], cd0, ce[0][p]);
                ce[1][p] = fma2(pr[1][p], cd1, ce[1][p]);
                ce[2][p] = fma2(pr[2][p], cd2, ce[2][p]);
            }
        }

        __syncthreads();
        if (t + 2 < NT) {
            #pragma unroll
            for (int j = 0; j < 4; ++j)
                stage_copy<TPB2>(sW + (size_t)(sset + j) * 2048,
                                 g_Wtp + (size_t)(cbeg + (t + 2) * 4 + j) * 2048, tid);
        }
    }

    #pragma unroll
    for (int q = 0; q < 3; ++q) {
        u64* d = (u64*)g_centp + (((size_t)cch * NPOS + pos0 + q) * FF + lane) * 8;
        #pragma unroll
        for (int p = 0; p < 8; ++p) d[p] = ce[q][p];
    }
}

// ---------------- squash 2: final output ------------------------------------
__global__ void k_squash2(float* __restrict__ out) {
    int t = blockIdx.x * blockDim.x + threadIdx.x;   // (pos,f)
    if (t >= NPOS * FF) return;
    float sx[8], sy[8];
    #pragma unroll
    for (int p = 0; p < 8; ++p) { sx[p] = 0.f; sy[p] = 0.f; }
    for (int ch = 0; ch < NCH2; ++ch) {
        const float2* s = g_centp + ((size_t)ch * NPOS * FF + t) * 8;
        #pragma unroll
        for (int p = 0; p < 8; ++p) { float2 v = s[p]; sx[p] += v.x; sy[p] += v.y; }
    }
    float sn = 0.f;
    #pragma unroll
    for (int p = 0; p < 8; ++p) sn += sx[p] * sx[p] + sy[p] * sy[p];
    float sc = (sn / (1.f + sn)) / sqrtf(sn + 1e-7f);
    float* d = out + (size_t)t * DOUT;
    #pragma unroll
    for (int p = 0; p < 8; ++p) { d[p] = sx[p] * sc; d[p + 8] = sy[p] * sc; }
}

// -----------------------------------------------------------------------------
extern "C" void kernel_launch(void* const* d_in, const int* in_sizes, int n_in,
                              void* d_out, int out_size) {
    const float* x = (const float*)d_in[0];
    const float* W = (const float*)d_in[1];
    if (n_in >= 2 && in_sizes[0] == (int)((size_t)FF * CCAP * DOUT * DIN)) {
        const float* t = x; x = W; W = t;
    }
    float* out = (float*)d_out;

    cudaFuncSetAttribute(k_pass1, cudaFuncAttributeMaxDynamicSharedMemorySize, SMEM_BYTES);
    cudaFuncSetAttribute(k_pass2, cudaFuncAttributeMaxDynamicSharedMemorySize, SMEM_BYTES);

    k_transpose<<<(CCAP * 8 * 32 + 255) / 256, 256>>>(W);
    k_pass1<<<dim3(NPB1, NCH1), TPB1, SMEM_BYTES>>>(x);
    k_squash1<<<(NPOS * FF + 255) / 256, 256>>>();
    k_pass2<<<dim3(NPB2, NCH2), TPB2, SMEM_BYTES>>>(x);
    k_squash2<<<(NPOS * FF + 255) / 256, 256>>>(out);
}

// round 7
// speedup vs baseline: 2.1020x; 1.0887x over previous
#include <cuda_runtime.h>
#include <math.h>
#include <stdint.h>

#define HIN     14
#define WIN     14
#define HO      12
#define WO      12
#define BATCH   4
#define FIN     32
#define DIN     8
#define FF      32
#define CCAP    288
#define DOUT    16
#define NPOS    (BATCH*HO*WO)   // 576

// both passes: 8 warps, 4 pos/warp -> 32 pos/CTA; 8 c-chunks of 36; grid 18x8=144
#define TPB     256
#define POSB    32
#define NPB     (NPOS/POSB)     // 18
#define NCH     8
#define CPC     (CCAP/NCH)      // 36  (9 quartets)

#define SMEM_BYTES (8 * 2048 * 8)   // 8 stages x 16KB = 128KB

typedef unsigned long long u64;

// ---------------- scratch (static device globals) ---------------------------
__device__ float2 g_Wtp[(size_t)CCAP*8*8*32];                 // [c][i][p][f] f32x2 pairs
__device__ float2 g_S1p[(size_t)NCH*NPOS*FF*8];               // pass1 partials
__device__ float2 g_out1p[(size_t)NPOS*FF*8];                 // squash(iter1)
__device__ float2 g_centp[(size_t)NCH*NPOS*FF*8];             // pass2 partial centroids

__device__ __constant__ int c_koff[9] = {0, 256, 512, 3584, 3840, 4096, 7168, 7424, 7680};

// ---------------- f32x2 helpers ---------------------------------------------
__device__ __forceinline__ u64 pk(float lo, float hi) {
    u64 r; asm("mov.b64 %0,{%1,%2};" : "=l"(r) : "f"(lo), "f"(hi)); return r;
}
__device__ __forceinline__ void upk(u64 v, float& a, float& b) {
    asm("mov.b64 {%0,%1},%2;" : "=f"(a), "=f"(b) : "l"(v));
}
__device__ __forceinline__ u64 fma2(u64 a, u64 b, u64 c) {
    u64 d; asm("fma.rn.f32x2 %0,%1,%2,%3;" : "=l"(d) : "l"(a), "l"(b), "l"(c)); return d;
}

// ---------------- cp.async helpers -------------------------------------------
__device__ __forceinline__ void cp16(uint32_t saddr, const void* gaddr) {
    asm volatile("cp.async.cg.shared.global [%0], [%1], 16;" :: "r"(saddr), "l"(gaddr));
}
__device__ __forceinline__ void stage_copy(u64* sdst, const float2* gsrc, int tid) {
    uint32_t s = (uint32_t)__cvta_generic_to_shared(sdst);
    const char* g = (const char*)gsrc;
    #pragma unroll
    for (int k = 0; k < 4; ++k) {          // 4 * 256 = 1024 x 16B
        int idx = tid + k * TPB;
        cp16(s + idx * 16, g + (size_t)idx * 16);
    }
    asm volatile("cp.async.commit_group;");
}
template<int N>
__device__ __forceinline__ void wait_cp() {
    asm volatile("cp.async.wait_group %0;" :: "n"(N));
}

// ---------------- W transform: W[f][c][o][i] -> Wtp[c][i][p][f] pairs --------
__global__ void k_transpose(const float* __restrict__ W) {
    int tid = blockIdx.x * blockDim.x + threadIdx.x;
    if (tid >= CCAP * 8 * 32) return;
    int f = tid & 31;
    int r = tid >> 5;
    int p = r & 7;
    int c = r >> 3;
    const float* row0 = W + (((size_t)f * CCAP + c) * DOUT + p) * DIN;
    const float* row8 = W + (((size_t)f * CCAP + c) * DOUT + p + 8) * DIN;
    float4 a0 = ((const float4*)row0)[0], a1 = ((const float4*)row0)[1];
    float4 b0 = ((const float4*)row8)[0], b1 = ((const float4*)row8)[1];
    float a[8] = {a0.x,a0.y,a0.z,a0.w,a1.x,a1.y,a1.z,a1.w};
    float b[8] = {b0.x,b0.y,b0.z,b0.w,b1.x,b1.y,b1.z,b1.w};
    #pragma unroll
    for (int i = 0; i < 8; ++i)
        g_Wtp[(((size_t)c * 8 + i) * 8 + p) * 32 + f] = make_float2(a[i], b[i]);
}

__device__ __forceinline__ const float* pos_base(const float* x, int pos) {
    int b = pos / (HO * WO);
    int r = pos % (HO * WO);
    int h = r / WO;
    int w = r % WO;
    return x + (((size_t)(b * HIN + h) * WIN) + w) * (FIN * DIN);
}

// ---------------- pass 1: partial sum over c of preds (4 pos/warp) ----------
__global__ void __launch_bounds__(TPB, 1) k_pass1(const float* __restrict__ x) {
    extern __shared__ u64 sW[];   // 8 stages x 2048 u64
    int tid  = threadIdx.x;
    int lane = tid & 31;
    int w    = tid >> 5;
    int pos0 = blockIdx.x * POSB + w * 4;
    int cch  = blockIdx.y;
    int cbeg = cch * CPC;
    const int NT = CPC / 4;   // 9 quartets

    const float* xb[4];
    #pragma unroll
    for (int q = 0; q < 4; ++q) xb[q] = pos_base(x, pos0 + q);

    u64 acc[4][8];
    #pragma unroll
    for (int q = 0; q < 4; ++q)
        #pragma unroll
        for (int p = 0; p < 8; ++p) acc[q][p] = 0ULL;

    #pragma unroll
    for (int j = 0; j < 4; ++j)
        stage_copy(sW + (size_t)j * 2048, g_Wtp + (size_t)(cbeg + j) * 2048, tid);
    #pragma unroll
    for (int j = 0; j < 4; ++j)
        stage_copy(sW + (size_t)(4 + j) * 2048, g_Wtp + (size_t)(cbeg + 4 + j) * 2048, tid);

    for (int t = 0; t < NT; ++t) {
        if (t + 1 < NT) wait_cp<4>(); else wait_cp<0>();
        __syncthreads();
        int sset = (t & 1) * 4;
        int qbeg = cbeg + t * 4;

        #pragma unroll
        for (int k = 0; k < 4; ++k) {
            int j = (w + k) & 3;          // rotated order per warp
            int c = qbeg + j;
            int off = c_koff[c >> 5] + (c & 31) * DIN;
            float xs[4][8];
            #pragma unroll
            for (int q = 0; q < 4; ++q) {
                float4 v0 = ((const float4*)(xb[q] + off))[0];
                float4 v1 = ((const float4*)(xb[q] + off))[1];
                xs[q][0]=v0.x; xs[q][1]=v0.y; xs[q][2]=v0.z; xs[q][3]=v0.w;
                xs[q][4]=v1.x; xs[q][5]=v1.y; xs[q][6]=v1.z; xs[q][7]=v1.w;
            }
            const u64* wb = sW + (size_t)(sset + j) * 2048;
            #pragma unroll
            for (int i = 0; i < 8; ++i) {
                u64 xd0 = pk(xs[0][i], xs[0][i]);
                u64 xd1 = pk(xs[1][i], xs[1][i]);
                u64 xd2 = pk(xs[2][i], xs[2][i]);
                u64 xd3 = pk(xs[3][i], xs[3][i]);
                #pragma unroll
                for (int p = 0; p < 8; ++p) {
                    u64 wv = wb[(i * 8 + p) * 32 + lane];
                    acc[0][p] = fma2(wv, xd0, acc[0][p]);
                    acc[1][p] = fma2(wv, xd1, acc[1][p]);
                    acc[2][p] = fma2(wv, xd2, acc[2][p]);
                    acc[3][p] = fma2(wv, xd3, acc[3][p]);
                }
            }
        }

        __syncthreads();
        if (t + 2 < NT) {
            #pragma unroll
            for (int j = 0; j < 4; ++j)
                stage_copy(sW + (size_t)(sset + j) * 2048,
                           g_Wtp + (size_t)(cbeg + (t + 2) * 4 + j) * 2048, tid);
        }
    }

    #pragma unroll
    for (int q = 0; q < 4; ++q) {
        u64* d = (u64*)g_S1p + (((size_t)cch * NPOS + pos0 + q) * FF + lane) * 8;
        #pragma unroll
        for (int p = 0; p < 8; ++p) d[p] = acc[q][p];
    }
}

// ---------------- squash 1 ---------------------------------------------------
__global__ void k_squash1() {
    int t = blockIdx.x * blockDim.x + threadIdx.x;   // (pos,f)
    if (t >= NPOS * FF) return;
    float sx[8], sy[8];
    #pragma unroll
    for (int p = 0; p < 8; ++p) { sx[p] = 0.f; sy[p] = 0.f; }
    for (int ch = 0; ch < NCH; ++ch) {
        const float2* s = g_S1p + ((size_t)ch * NPOS * FF + t) * 8;
        #pragma unroll
        for (int p = 0; p < 8; ++p) { float2 v = s[p]; sx[p] += v.x; sy[p] += v.y; }
    }
    float sn = 0.f;
    #pragma unroll
    for (int p = 0; p < 8; ++p) {
        sx[p] *= (1.f / 32.f); sy[p] *= (1.f / 32.f);
        sn += sx[p] * sx[p] + sy[p] * sy[p];
    }
    float sc = (sn / (1.f + sn)) / sqrtf(sn + 1e-7f);
    float2* d = g_out1p + (size_t)t * 8;
    #pragma unroll
    for (int p = 0; p < 8; ++p) d[p] = make_float2(sx[p] * sc, sy[p] * sc);
}

// ---------------- pass 2: fused agreement/softmax(F)/centroid (4 pos/warp) --
__global__ void __launch_bounds__(TPB, 1) k_pass2(const float* __restrict__ x) {
    extern __shared__ u64 sW[];   // 8 stages x 2048 u64
    int tid  = threadIdx.x;
    int lane = tid & 31;
    int w    = tid >> 5;
    int pos0 = blockIdx.x * POSB + w * 4;
    int cch  = blockIdx.y;
    int cbeg = cch * CPC;
    const int NT = CPC / 4;   // 9 quartets

    const float* xb[4];
    #pragma unroll
    for (int q = 0; q < 4; ++q) xb[q] = pos_base(x, pos0 + q);

    u64 o1[4][8];
    #pragma unroll
    for (int q = 0; q < 4; ++q) {
        const u64* s = (const u64*)g_out1p + (((size_t)(pos0 + q) * FF) + lane) * 8;
        #pragma unroll
        for (int p = 0; p < 8; ++p) o1[q][p] = s[p];
    }

    u64 ce[4][8];
    #pragma unroll
    for (int q = 0; q < 4; ++q)
        #pragma unroll
        for (int p = 0; p < 8; ++p) ce[q][p] = 0ULL;

    #pragma unroll
    for (int j = 0; j < 4; ++j)
        stage_copy(sW + (size_t)j * 2048, g_Wtp + (size_t)(cbeg + j) * 2048, tid);
    #pragma unroll
    for (int j = 0; j < 4; ++j)
        stage_copy(sW + (size_t)(4 + j) * 2048, g_Wtp + (size_t)(cbeg + 4 + j) * 2048, tid);

    for (int t = 0; t < NT; ++t) {
        if (t + 1 < NT) wait_cp<4>(); else wait_cp<0>();
        __syncthreads();
        int sset = (t & 1) * 4;
        int qbeg = cbeg + t * 4;

        #pragma unroll
        for (int k = 0; k < 4; ++k) {
            int j = (w + k) & 3;          // rotated order per warp -> phase mixing
            int c = qbeg + j;
            int off = c_koff[c >> 5] + (c & 31) * DIN;
            float xs[4][8];
            #pragma unroll
            for (int q = 0; q < 4; ++q) {
                float4 v0 = ((const float4*)(xb[q] + off))[0];
                float4 v1 = ((const float4*)(xb[q] + off))[1];
                xs[q][0]=v0.x; xs[q][1]=v0.y; xs[q][2]=v0.z; xs[q][3]=v0.w;
                xs[q][4]=v1.x; xs[q][5]=v1.y; xs[q][6]=v1.z; xs[q][7]=v1.w;
            }

            u64 pr[4][8];
            #pragma unroll
            for (int q = 0; q < 4; ++q)
                #pragma unroll
                for (int p = 0; p < 8; ++p) pr[q][p] = 0ULL;

            const u64* wb = sW + (size_t)(sset + j) * 2048;
            #pragma unroll
            for (int i = 0; i < 8; ++i) {
                u64 xd0 = pk(xs[0][i], xs[0][i]);
                u64 xd1 = pk(xs[1][i], xs[1][i]);
                u64 xd2 = pk(xs[2][i], xs[2][i]);
                u64 xd3 = pk(xs[3][i], xs[3][i]);
                #pragma unroll
                for (int p = 0; p < 8; ++p) {
                    u64 wv = wb[(i * 8 + p) * 32 + lane];
                    pr[0][p] = fma2(wv, xd0, pr[0][p]);
                    pr[1][p] = fma2(wv, xd1, pr[1][p]);
                    pr[2][p] = fma2(wv, xd2, pr[2][p]);
                    pr[3][p] = fma2(wv, xd3, pr[3][p]);
                }
            }

            // agreement dots (packed), horizontal add; no max-subtraction
            float e[4];
            #pragma unroll
            for (int q = 0; q < 4; ++q) {
                u64 a = 0ULL;
                #pragma unroll
                for (int p = 0; p < 8; ++p) a = fma2(pr[q][p], o1[q][p], a);
                float l, h;
                upk(a, l, h);
                e[q] = __expf(l + h);
            }

            // 4 independent butterfly sums over f (lanes) — fully pipelined
            float s0 = e[0], s1 = e[1], s2 = e[2], s3 = e[3];
            #pragma unroll
            for (int d = 16; d > 0; d >>= 1) {
                s0 += __shfl_xor_sync(0xffffffffu, s0, d);
                s1 += __shfl_xor_sync(0xffffffffu, s1, d);
                s2 += __shfl_xor_sync(0xffffffffu, s2, d);
                s3 += __shfl_xor_sync(0xffffffffu, s3, d);
            }
            float cc[4] = { __fdividef(e[0], s0), __fdividef(e[1], s1),
                            __fdividef(e[2], s2), __fdividef(e[3], s3) };

            #pragma unroll
            for (int q = 0; q < 4; ++q) {
                u64 cd = pk(cc[q], cc[q]);
                #pragma unroll
                for (int p = 0; p < 8; ++p)
                    ce[q][p] = fma2(pr[q][p], cd, ce[q][p]);
            }
        }

        __syncthreads();
        if (t + 2 < NT) {
            #pragma unroll
            for (int j = 0; j < 4; ++j)
                stage_copy(sW + (size_t)(sset + j) * 2048,
                           g_Wtp + (size_t)(cbeg + (t + 2) * 4 + j) * 2048, tid);
        }
    }

    #pragma unroll
    for (int q = 0; q < 4; ++q) {
        u64* d = (u64*)g_centp + (((size_t)cch * NPOS + pos0 + q) * FF + lane) * 8;
        #pragma unroll
        for (int p = 0; p < 8; ++p) d[p] = ce[q][p];
    }
}

// ---------------- squash 2: final output ------------------------------------
__global__ void k_squash2(float* __restrict__ out) {
    int t = blockIdx.x * blockDim.x + threadIdx.x;   // (pos,f)
    if (t >= NPOS * FF) return;
    float sx[8], sy[8];
    #pragma unroll
    for (int p = 0; p < 8; ++p) { sx[p] = 0.f; sy[p] = 0.f; }
    for (int ch = 0; ch < NCH; ++ch) {
        const float2* s = g_centp + ((size_t)ch * NPOS * FF + t) * 8;
        #pragma unroll
        for (int p = 0; p < 8; ++p) { float2 v = s[p]; sx[p] += v.x; sy[p] += v.y; }
    }
    float sn = 0.f;
    #pragma unroll
    for (int p = 0; p < 8; ++p) sn += sx[p] * sx[p] + sy[p] * sy[p];
    float sc = (sn / (1.f + sn)) / sqrtf(sn + 1e-7f);
    float* d = out + (size_t)t * DOUT;
    #pragma unroll
    for (int p = 0; p < 8; ++p) { d[p] = sx[p] * sc; d[p + 8] = sy[p] * sc; }
}

// -----------------------------------------------------------------------------
extern "C" void kernel_launch(void* const* d_in, const int* in_sizes, int n_in,
                              void* d_out, int out_size) {
    const float* x = (const float*)d_in[0];
    const float* W = (const float*)d_in[1];
    if (n_in >= 2 && in_sizes[0] == (int)((size_t)FF * CCAP * DOUT * DIN)) {
        const float* t = x; x = W; W = t;
    }
    float* out = (float*)d_out;

    cudaFuncSetAttribute(k_pass1, cudaFuncAttributeMaxDynamicSharedMemorySize, SMEM_BYTES);
    cudaFuncSetAttribute(k_pass2, cudaFuncAttributeMaxDynamicSharedMemorySize, SMEM_BYTES);

    k_transpose<<<(CCAP * 8 * 32 + 255) / 256, 256>>>(W);
    k_pass1<<<dim3(NPB, NCH), TPB, SMEM_BYTES>>>(x);
    k_squash1<<<(NPOS * FF + 255) / 256, 256>>>();
    k_pass2<<<dim3(NPB, NCH), TPB, SMEM_BYTES>>>(x);
    k_squash2<<<(NPOS * FF + 255) / 256, 256>>>(out);
}